// round 1
// baseline (speedup 1.0000x reference)
#include <cuda_runtime.h>
#include <math.h>
#include <stdint.h>

#define B_   4
#define T_   4096
#define H_   1024
#define S_   64
#define M_   (B_*T_)     // 16384 rows
#define NCH  64          // scan chunks
#define TC   64          // chunk length (NCH*TC == T_)
#define LN_EPSF 1e-5f

// ---- scratch (static __device__ arrays; no allocation APIs allowed) ----
__device__ float g_u[M_*S_];        // driving term u = gate * Bx         (4 MB)
__device__ float g_L[B_*NCH*S_];    // per-chunk local final states       (64 KB)
__device__ float g_E[B_*NCH*S_];    // per-chunk entering states          (64 KB)
__device__ float g_states[M_*S_];   // full scan states                   (4 MB)
__device__ float g_hn[M_*H_];       // layernormed hidden                 (64 MB)

// ============================================================
// Kernel A: u = sigmoid(x @ Wg^T + bg) * (x @ WB^T)
// 64x64 block tile, K-tile 16, 256 threads, 4x4 per-thread, dual accumulators.
// ============================================================
__global__ void __launch_bounds__(256) uGemm(const float* __restrict__ x,
                                             const float* __restrict__ Wg,
                                             const float* __restrict__ bg,
                                             const float* __restrict__ WB) {
    __shared__ float sx[16][68];
    __shared__ float sg[16][68];
    __shared__ float sb[16][68];
    const int tid = threadIdx.x;
    const int tx = tid & 15, ty = tid >> 4;
    const int rowBase = blockIdx.x * 64;
    const int lr = tid >> 2;          // 0..63
    const int lk = (tid & 3) * 4;     // 0,4,8,12

    float accG[4][4] = {};
    float accB[4][4] = {};

    for (int k0 = 0; k0 < H_; k0 += 16) {
        float4 vx = *(const float4*)&x [(size_t)(rowBase + lr) * H_ + k0 + lk];
        float4 vg = *(const float4*)&Wg[(size_t)lr * H_ + k0 + lk];
        float4 vb = *(const float4*)&WB[(size_t)lr * H_ + k0 + lk];
        sx[lk+0][lr]=vx.x; sx[lk+1][lr]=vx.y; sx[lk+2][lr]=vx.z; sx[lk+3][lr]=vx.w;
        sg[lk+0][lr]=vg.x; sg[lk+1][lr]=vg.y; sg[lk+2][lr]=vg.z; sg[lk+3][lr]=vg.w;
        sb[lk+0][lr]=vb.x; sb[lk+1][lr]=vb.y; sb[lk+2][lr]=vb.z; sb[lk+3][lr]=vb.w;
        __syncthreads();
        #pragma unroll
        for (int k = 0; k < 16; k++) {
            float a[4], g[4], b[4];
            #pragma unroll
            for (int i = 0; i < 4; i++) a[i] = sx[k][ty*4 + i];
            #pragma unroll
            for (int j = 0; j < 4; j++) { g[j] = sg[k][tx*4 + j]; b[j] = sb[k][tx*4 + j]; }
            #pragma unroll
            for (int i = 0; i < 4; i++)
                #pragma unroll
                for (int j = 0; j < 4; j++) {
                    accG[i][j] = fmaf(a[i], g[j], accG[i][j]);
                    accB[i][j] = fmaf(a[i], b[j], accB[i][j]);
                }
        }
        __syncthreads();
    }

    #pragma unroll
    for (int i = 0; i < 4; i++) {
        int row = rowBase + ty*4 + i;
        #pragma unroll
        for (int j = 0; j < 4; j++) {
            int s = tx*4 + j;
            float gate = 1.0f / (1.0f + expf(-(accG[i][j] + bg[s])));
            g_u[(size_t)row * S_ + s] = gate * accB[i][j];
        }
    }
}

// ============================================================
// Kernel B1: per-chunk local scan (zero-init) -> chunk carries
// grid = B*NCH blocks, S_ threads
// ============================================================
__global__ void scanLocal(const float* __restrict__ A_log) {
    const int b = blockIdx.x / NCH, c = blockIdx.x % NCH;
    const int s = threadIdx.x;
    const float a = expf(A_log[s]);
    const float* up = &g_u[((size_t)(b * T_) + c * TC) * S_ + s];
    float st = 0.0f;
    #pragma unroll 8
    for (int i = 0; i < TC; i++) st = fmaf(a, st, up[i * S_]);
    g_L[((size_t)b * NCH + c) * S_ + s] = st;
}

// ============================================================
// Kernel B2: serial cross-chunk scan (tiny: 256 threads x 64 steps)
// also emits final_state if requested
// ============================================================
__global__ void scanCarry(const float* __restrict__ A_log, float* __restrict__ finalState) {
    const int tid = threadIdx.x;              // 0..255 = B*S
    const int b = tid / S_, s = tid % S_;
    const float a = expf(A_log[s]);
    float aTC = 1.0f;
    #pragma unroll
    for (int i = 0; i < TC; i++) aTC *= a;    // a^64
    float E = 0.0f;
    for (int c = 0; c < NCH; c++) {
        g_E[((size_t)b * NCH + c) * S_ + s] = E;
        E = fmaf(aTC, E, g_L[((size_t)b * NCH + c) * S_ + s]);
    }
    if (finalState) finalState[b * S_ + s] = E;
}

// ============================================================
// Kernel B3: full states with correct entering state
// ============================================================
__global__ void scanStates(const float* __restrict__ A_log) {
    const int b = blockIdx.x / NCH, c = blockIdx.x % NCH;
    const int s = threadIdx.x;
    const float a = expf(A_log[s]);
    float st = g_E[((size_t)b * NCH + c) * S_ + s];
    const size_t base = ((size_t)(b * T_) + c * TC) * S_ + s;
    #pragma unroll 8
    for (int i = 0; i < TC; i++) {
        st = fmaf(a, st, g_u[base + (size_t)i * S_]);
        g_states[base + (size_t)i * S_] = st;
    }
}

// ============================================================
// Kernel C: h = states @ WC^T + (D+1)*x ; LayerNorm -> g_hn
// one block per row, 256 threads x 4 h-elems
// ============================================================
__global__ void __launch_bounds__(256) yLN(const float* __restrict__ x,
                                           const float* __restrict__ WC,
                                           const float* __restrict__ Dv,
                                           const float* __restrict__ gamma,
                                           const float* __restrict__ beta) {
    const int row = blockIdx.x;
    const int tid = threadIdx.x;
    __shared__ float st[S_];
    __shared__ float redS[32], redQ[32];
    if (tid < S_) st[tid] = g_states[(size_t)row * S_ + tid];
    __syncthreads();

    float hv[4];
    float sum = 0.0f, sq = 0.0f;
    #pragma unroll
    for (int q = 0; q < 4; q++) {
        const int h = tid + q * 256;
        const float4* wc4 = (const float4*)&WC[(size_t)h * S_];
        const float4* st4 = (const float4*)st;
        float y = 0.0f;
        #pragma unroll
        for (int s4 = 0; s4 < S_/4; s4++) {
            float4 w = wc4[s4], t = st4[s4];
            y = fmaf(w.x, t.x, y); y = fmaf(w.y, t.y, y);
            y = fmaf(w.z, t.z, y); y = fmaf(w.w, t.w, y);
        }
        float v = fmaf(Dv[h] + 1.0f, x[(size_t)row * H_ + h], y);
        hv[q] = v; sum += v; sq = fmaf(v, v, sq);
    }

    // block reduce (sum, sq)
    #pragma unroll
    for (int o = 16; o > 0; o >>= 1) {
        sum += __shfl_down_sync(0xffffffffu, sum, o);
        sq  += __shfl_down_sync(0xffffffffu, sq,  o);
    }
    const int lane = tid & 31, w = tid >> 5;
    if (lane == 0) { redS[w] = sum; redQ[w] = sq; }
    __syncthreads();
    if (w == 0) {
        float vs = lane < 8 ? redS[lane] : 0.0f;
        float vq = lane < 8 ? redQ[lane] : 0.0f;
        #pragma unroll
        for (int o = 4; o > 0; o >>= 1) {
            vs += __shfl_down_sync(0xffffffffu, vs, o);
            vq += __shfl_down_sync(0xffffffffu, vq, o);
        }
        if (lane == 0) { redS[0] = vs; redQ[0] = vq; }
    }
    __syncthreads();
    const float mu  = redS[0] * (1.0f / H_);
    const float var = redQ[0] * (1.0f / H_) - mu * mu;
    const float inv = rsqrtf(var + LN_EPSF);
    #pragma unroll
    for (int q = 0; q < 4; q++) {
        const int h = tid + q * 256;
        g_hn[(size_t)row * H_ + h] = fmaf((hv[q] - mu) * inv, gamma[h], beta[h]);
    }
}

// ============================================================
// Kernel D: out = hn @ Wout^T + bout  (M=16384, N=1024, K=1024)
// 128x128 tile, BK=16, 256 threads, 8x8 per-thread using packed fma.rn.f32x2
// ============================================================
__device__ __forceinline__ unsigned long long fma_f32x2(unsigned long long a,
                                                        unsigned long long b,
                                                        unsigned long long c) {
    unsigned long long d;
    asm("fma.rn.f32x2 %0, %1, %2, %3;" : "=l"(d) : "l"(a), "l"(b), "l"(c));
    return d;
}
__device__ __forceinline__ unsigned long long pack2(float lo, float hi) {
    unsigned long long r;
    asm("mov.b64 %0, {%1, %2};" : "=l"(r) : "f"(lo), "f"(hi));
    return r;
}

__global__ void __launch_bounds__(256) outGemm(const float* __restrict__ Wout,
                                               const float* __restrict__ bout,
                                               float* __restrict__ out) {
    __shared__ float sA[16][132];
    __shared__ float sB[16][132];
    const int tid = threadIdx.x;
    const int rowBase = blockIdx.x * 128;
    const int colBase = blockIdx.y * 128;
    const int rg = (tid >> 4) * 8;    // row group within tile
    const int cg = (tid & 15) * 8;    // col group within tile
    const int lr = tid >> 1;          // 0..127 load row
    const int lk = (tid & 1) * 8;     // 0 or 8

    unsigned long long acc[8][4];
    #pragma unroll
    for (int i = 0; i < 8; i++)
        #pragma unroll
        for (int j = 0; j < 4; j++) acc[i][j] = 0ULL;

    for (int k0 = 0; k0 < H_; k0 += 16) {
        float4 a0 = *(const float4*)&g_hn[(size_t)(rowBase + lr) * H_ + k0 + lk];
        float4 a1 = *(const float4*)&g_hn[(size_t)(rowBase + lr) * H_ + k0 + lk + 4];
        float4 b0 = *(const float4*)&Wout[(size_t)(colBase + lr) * H_ + k0 + lk];
        float4 b1 = *(const float4*)&Wout[(size_t)(colBase + lr) * H_ + k0 + lk + 4];
        sA[lk+0][lr]=a0.x; sA[lk+1][lr]=a0.y; sA[lk+2][lr]=a0.z; sA[lk+3][lr]=a0.w;
        sA[lk+4][lr]=a1.x; sA[lk+5][lr]=a1.y; sA[lk+6][lr]=a1.z; sA[lk+7][lr]=a1.w;
        sB[lk+0][lr]=b0.x; sB[lk+1][lr]=b0.y; sB[lk+2][lr]=b0.z; sB[lk+3][lr]=b0.w;
        sB[lk+4][lr]=b1.x; sB[lk+5][lr]=b1.y; sB[lk+6][lr]=b1.z; sB[lk+7][lr]=b1.w;
        __syncthreads();
        #pragma unroll
        for (int k = 0; k < 16; k++) {
            float4 av0 = *(const float4*)&sA[k][rg];
            float4 av1 = *(const float4*)&sA[k][rg + 4];
            const unsigned long long* bp = (const unsigned long long*)&sB[k][cg];
            unsigned long long b2[4];
            #pragma unroll
            for (int j = 0; j < 4; j++) b2[j] = bp[j];
            float a[8] = {av0.x, av0.y, av0.z, av0.w, av1.x, av1.y, av1.z, av1.w};
            #pragma unroll
            for (int i = 0; i < 8; i++) {
                unsigned long long ap = pack2(a[i], a[i]);
                #pragma unroll
                for (int j = 0; j < 4; j++)
                    acc[i][j] = fma_f32x2(ap, b2[j], acc[i][j]);
            }
        }
        __syncthreads();
    }

    #pragma unroll
    for (int i = 0; i < 8; i++) {
        const int r = rowBase + rg + i;
        #pragma unroll
        for (int j = 0; j < 4; j++) {
            const int c = colBase + cg + 2 * j;
            float2 v = *(float2*)&acc[i][j];
            v.x += bout[c];
            v.y += bout[c + 1];
            *(float2*)&out[(size_t)r * H_ + c] = v;
        }
    }
}

// ============================================================
// launch
// ============================================================
extern "C" void kernel_launch(void* const* d_in, const int* in_sizes, int n_in,
                              void* d_out, int out_size) {
    const float* x     = (const float*)d_in[0];
    const float* A_log = (const float*)d_in[1];
    const float* WB    = (const float*)d_in[2];
    const float* WC    = (const float*)d_in[3];
    const float* Dv    = (const float*)d_in[4];
    const float* Wg    = (const float*)d_in[5];
    const float* bg    = (const float*)d_in[6];
    const float* Wout  = (const float*)d_in[7];
    const float* bout  = (const float*)d_in[8];
    const float* gamma = (const float*)d_in[9];
    const float* beta  = (const float*)d_in[10];

    float* out = (float*)d_out;
    float* finalState = (out_size >= M_ * H_ + B_ * S_) ? out + (size_t)M_ * H_ : nullptr;

    uGemm<<<M_/64, 256>>>(x, Wg, bg, WB);
    scanLocal<<<B_*NCH, S_>>>(A_log);
    scanCarry<<<1, B_*S_>>>(A_log, finalState);
    scanStates<<<B_*NCH, S_>>>(A_log);
    yLN<<<M_, 256>>>(x, WC, Dv, gamma, beta);
    dim3 gD(M_/128, H_/128);
    outGemm<<<gD, 256>>>(Wout, bout, out);
}

// round 4
// speedup vs baseline: 1.3351x; 1.3351x over previous
#include <cuda_runtime.h>
#include <cuda_bf16.h>
#include <math.h>
#include <stdint.h>

#define B_   4
#define T_   4096
#define H_   1024
#define S_   64
#define M_   (B_*T_)     // 16384 rows
#define NCH  64
#define TC   64
#define LN_EPSF 1e-5f

// ---- scratch ----
__device__ float g_u[M_*S_];
__device__ float g_L[B_*NCH*S_];
__device__ float g_E[B_*NCH*S_];
__device__ float g_states[M_*S_];
__device__ __nv_bfloat16 g_hn_hi[(size_t)M_*H_];   // 32 MB
__device__ __nv_bfloat16 g_hn_lo[(size_t)M_*H_];   // 32 MB
__device__ __nv_bfloat16 g_wo_hi[(size_t)H_*H_];   // 2 MB
__device__ __nv_bfloat16 g_wo_lo[(size_t)H_*H_];   // 2 MB

// ============================================================
// PTX helpers (sm_80+ portable: cp.async, ldmatrix, mma.sync)
// ============================================================
__device__ __forceinline__ uint32_t smem_u32(const void* p) {
    uint32_t a;
    asm("{ .reg .u64 t; cvta.to.shared.u64 t, %1; cvt.u32.u64 %0, t; }" : "=r"(a) : "l"(p));
    return a;
}
#define CP_ASYNC16(dst, src) \
    asm volatile("cp.async.cg.shared.global [%0], [%1], 16;" :: "r"(dst), "l"(src) : "memory")
#define CP_COMMIT() asm volatile("cp.async.commit_group;" ::: "memory")
#define CP_WAIT0()  asm volatile("cp.async.wait_group 0;" ::: "memory")

#define LDMX4(r, addr) \
    asm volatile("ldmatrix.sync.aligned.m8n8.x4.shared.b16 {%0,%1,%2,%3}, [%4];" \
        : "=r"((r)[0]), "=r"((r)[1]), "=r"((r)[2]), "=r"((r)[3]) : "r"(addr))

#define MMA_BF16(c, a, b0v, b1v) \
    asm volatile("mma.sync.aligned.m16n8k16.row.col.f32.bf16.bf16.f32 " \
        "{%0,%1,%2,%3},{%4,%5,%6,%7},{%8,%9},{%0,%1,%2,%3};" \
        : "+f"((c)[0]), "+f"((c)[1]), "+f"((c)[2]), "+f"((c)[3]) \
        : "r"((a)[0]), "r"((a)[1]), "r"((a)[2]), "r"((a)[3]), "r"(b0v), "r"(b1v))

// ============================================================
// Kernel A: u = sigmoid(x @ Wg^T + bg) * (x @ WB^T)   (fp32)
// ============================================================
__global__ void __launch_bounds__(256) uGemm(const float* __restrict__ x,
                                             const float* __restrict__ Wg,
                                             const float* __restrict__ bg,
                                             const float* __restrict__ WB) {
    __shared__ float sx[16][68];
    __shared__ float sg[16][68];
    __shared__ float sb[16][68];
    const int tid = threadIdx.x;
    const int tx = tid & 15, ty = tid >> 4;
    const int rowBase = blockIdx.x * 64;
    const int lr = tid >> 2;
    const int lk = (tid & 3) * 4;

    float accG[4][4] = {};
    float accB[4][4] = {};

    for (int k0 = 0; k0 < H_; k0 += 16) {
        float4 vx = *(const float4*)&x [(size_t)(rowBase + lr) * H_ + k0 + lk];
        float4 vg = *(const float4*)&Wg[(size_t)lr * H_ + k0 + lk];
        float4 vb = *(const float4*)&WB[(size_t)lr * H_ + k0 + lk];
        sx[lk+0][lr]=vx.x; sx[lk+1][lr]=vx.y; sx[lk+2][lr]=vx.z; sx[lk+3][lr]=vx.w;
        sg[lk+0][lr]=vg.x; sg[lk+1][lr]=vg.y; sg[lk+2][lr]=vg.z; sg[lk+3][lr]=vg.w;
        sb[lk+0][lr]=vb.x; sb[lk+1][lr]=vb.y; sb[lk+2][lr]=vb.z; sb[lk+3][lr]=vb.w;
        __syncthreads();
        #pragma unroll
        for (int k = 0; k < 16; k++) {
            float a[4], g[4], b[4];
            #pragma unroll
            for (int i = 0; i < 4; i++) a[i] = sx[k][ty*4 + i];
            #pragma unroll
            for (int j = 0; j < 4; j++) { g[j] = sg[k][tx*4 + j]; b[j] = sb[k][tx*4 + j]; }
            #pragma unroll
            for (int i = 0; i < 4; i++)
                #pragma unroll
                for (int j = 0; j < 4; j++) {
                    accG[i][j] = fmaf(a[i], g[j], accG[i][j]);
                    accB[i][j] = fmaf(a[i], b[j], accB[i][j]);
                }
        }
        __syncthreads();
    }
    #pragma unroll
    for (int i = 0; i < 4; i++) {
        int row = rowBase + ty*4 + i;
        #pragma unroll
        for (int j = 0; j < 4; j++) {
            int s = tx*4 + j;
            float gate = 1.0f / (1.0f + expf(-(accG[i][j] + bg[s])));
            g_u[(size_t)row * S_ + s] = gate * accB[i][j];
        }
    }
}

// ============================================================
// Scan kernels
// ============================================================
__global__ void scanLocal(const float* __restrict__ A_log) {
    const int b = blockIdx.x / NCH, c = blockIdx.x % NCH;
    const int s = threadIdx.x;
    const float a = expf(A_log[s]);
    const float* up = &g_u[((size_t)(b * T_) + c * TC) * S_ + s];
    float st = 0.0f;
    #pragma unroll 8
    for (int i = 0; i < TC; i++) st = fmaf(a, st, up[i * S_]);
    g_L[((size_t)b * NCH + c) * S_ + s] = st;
}

__global__ void scanCarry(const float* __restrict__ A_log, float* __restrict__ finalState) {
    const int tid = threadIdx.x;
    const int b = tid / S_, s = tid % S_;
    const float a = expf(A_log[s]);
    float aTC = 1.0f;
    #pragma unroll
    for (int i = 0; i < TC; i++) aTC *= a;
    float E = 0.0f;
    for (int c = 0; c < NCH; c++) {
        g_E[((size_t)b * NCH + c) * S_ + s] = E;
        E = fmaf(aTC, E, g_L[((size_t)b * NCH + c) * S_ + s]);
    }
    if (finalState) finalState[b * S_ + s] = E;
}

__global__ void scanStates(const float* __restrict__ A_log) {
    const int b = blockIdx.x / NCH, c = blockIdx.x % NCH;
    const int s = threadIdx.x;
    const float a = expf(A_log[s]);
    float st = g_E[((size_t)b * NCH + c) * S_ + s];
    const size_t base = ((size_t)(b * T_) + c * TC) * S_ + s;
    #pragma unroll 8
    for (int i = 0; i < TC; i++) {
        st = fmaf(a, st, g_u[base + (size_t)i * S_]);
        g_states[base + (size_t)i * S_] = st;
    }
}

// ============================================================
// Kernel C: h = states @ WC^T + (D+1)*x ; LN -> planar hi/lo bf16
// ============================================================
__global__ void __launch_bounds__(256) yLN(const float* __restrict__ x,
                                           const float* __restrict__ WC,
                                           const float* __restrict__ Dv,
                                           const float* __restrict__ gamma,
                                           const float* __restrict__ beta) {
    const int row = blockIdx.x;
    const int tid = threadIdx.x;
    __shared__ float st[S_];
    __shared__ float redS[32], redQ[32];
    if (tid < S_) st[tid] = g_states[(size_t)row * S_ + tid];
    __syncthreads();

    float hv[4];
    float sum = 0.0f, sq = 0.0f;
    #pragma unroll
    for (int q = 0; q < 4; q++) {
        const int h = tid + q * 256;
        const float4* wc4 = (const float4*)&WC[(size_t)h * S_];
        const float4* st4 = (const float4*)st;
        float y = 0.0f;
        #pragma unroll
        for (int s4 = 0; s4 < S_/4; s4++) {
            float4 w = wc4[s4], t = st4[s4];
            y = fmaf(w.x, t.x, y); y = fmaf(w.y, t.y, y);
            y = fmaf(w.z, t.z, y); y = fmaf(w.w, t.w, y);
        }
        float v = fmaf(Dv[h] + 1.0f, x[(size_t)row * H_ + h], y);
        hv[q] = v; sum += v; sq = fmaf(v, v, sq);
    }
    #pragma unroll
    for (int o = 16; o > 0; o >>= 1) {
        sum += __shfl_down_sync(0xffffffffu, sum, o);
        sq  += __shfl_down_sync(0xffffffffu, sq,  o);
    }
    const int lane = tid & 31, w = tid >> 5;
    if (lane == 0) { redS[w] = sum; redQ[w] = sq; }
    __syncthreads();
    if (w == 0) {
        float vs = lane < 8 ? redS[lane] : 0.0f;
        float vq = lane < 8 ? redQ[lane] : 0.0f;
        #pragma unroll
        for (int o = 4; o > 0; o >>= 1) {
            vs += __shfl_down_sync(0xffffffffu, vs, o);
            vq += __shfl_down_sync(0xffffffffu, vq, o);
        }
        if (lane == 0) { redS[0] = vs; redQ[0] = vq; }
    }
    __syncthreads();
    const float mu  = redS[0] * (1.0f / H_);
    const float var = redQ[0] * (1.0f / H_) - mu * mu;
    const float inv = rsqrtf(var + LN_EPSF);
    #pragma unroll
    for (int q = 0; q < 4; q++) {
        const int h = tid + q * 256;
        float v = fmaf((hv[q] - mu) * inv, gamma[h], beta[h]);
        __nv_bfloat16 hi = __float2bfloat16(v);
        g_hn_hi[(size_t)row * H_ + h] = hi;
        g_hn_lo[(size_t)row * H_ + h] = __float2bfloat16(v - __bfloat162float(hi));
    }
}

// ============================================================
// Kernel W: split Wout into planar hi/lo bf16
// ============================================================
__global__ void __launch_bounds__(256) wSplit(const float* __restrict__ Wout) {
    const int base = (blockIdx.x * 256 + threadIdx.x) * 4;
    #pragma unroll
    for (int t = 0; t < 4; t++) {
        float v = Wout[base + t];
        __nv_bfloat16 hi = __float2bfloat16(v);
        g_wo_hi[base + t] = hi;
        g_wo_lo[base + t] = __float2bfloat16(v - __bfloat162float(hi));
    }
}

// ============================================================
// Kernel D: out = hn @ Wout^T + bout via mma.sync bf16.
// Split-precision 3-segment GEMM, effective K' = 3072:
//   seg0: A=hn_hi B=wo_hi ; seg1: A=hn_lo B=wo_hi ; seg2: A=hn_hi B=wo_lo
// CTA 128x128, warp 64x32, KT=64, double-buffered cp.async.
// smem rows padded to 144 B -> conflict-free ldmatrix.
// ============================================================
#define KT     64
#define SROW_B 144           // bytes per smem row (72 bf16)
#define STILE  (128*SROW_B)  // 18432 bytes per tile
#define SMEM_D (4*STILE)     // 73728: 2 stages x (A+B)
#define SEG_IT (H_/KT)       // 16 iterations per segment
#define NIT    (3*SEG_IT)    // 48

__global__ void __launch_bounds__(256, 2) outGemmMMA(const float* __restrict__ bout,
                                                     float* __restrict__ out) {
    extern __shared__ char sm[];
    const uint32_t smb = smem_u32(sm);
    const int tid = threadIdx.x;
    const int lane = tid & 31, w = tid >> 5;
    const int wr = w >> 2, wc = w & 3;          // warp grid 2 x 4
    const int rowBase = blockIdx.x * 128;
    const int colBase = blockIdx.y * 128;

    auto loadStage = [&](int stage, int it) {
        const int seg = it >> 4;                 // 0,1,2
        const int k0  = (it & 15) * KT;
        const __nv_bfloat16* Asrc = (seg == 1) ? g_hn_lo : g_hn_hi;
        const __nv_bfloat16* Bsrc = (seg == 2) ? g_wo_lo : g_wo_hi;
        const uint32_t aB = smb + stage * 2 * STILE;
        const uint32_t bB = aB + STILE;
        #pragma unroll
        for (int t = 0; t < 4; t++) {
            const int c = tid + t * 256;          // 0..1023
            const int r = c >> 3, j = c & 7;      // row, 16B chunk
            const __nv_bfloat16* sA = &Asrc[(size_t)(rowBase + r) * H_ + k0 + j * 8];
            const __nv_bfloat16* sB = &Bsrc[(size_t)(colBase + r) * H_ + k0 + j * 8];
            CP_ASYNC16(aB + r * SROW_B + j * 16, sA);
            CP_ASYNC16(bB + r * SROW_B + j * 16, sB);
        }
        CP_COMMIT();
    };

    float acc[4][4][4];
    #pragma unroll
    for (int i = 0; i < 4; i++)
        #pragma unroll
        for (int j = 0; j < 4; j++)
            #pragma unroll
            for (int q = 0; q < 4; q++) acc[i][j][q] = 0.0f;

    loadStage(0, 0);

    for (int it = 0; it < NIT; it++) {
        const int stage = it & 1;
        CP_WAIT0();
        __syncthreads();
        if (it + 1 < NIT) loadStage(stage ^ 1, it + 1);

        const uint32_t aT = smb + stage * 2 * STILE;
        const uint32_t bT = aT + STILE;
        #pragma unroll
        for (int ks = 0; ks < 4; ks++) {
            const int kb = ks * 32;               // byte offset of k within row
            uint32_t af[4][4];
            #pragma unroll
            for (int mi = 0; mi < 4; mi++) {
                const int m0 = wr * 64 + mi * 16;
                const uint32_t addr = aT + (uint32_t)(m0 + (lane & 15)) * SROW_B
                                      + kb + ((lane >> 4) << 4);
                LDMX4(af[mi], addr);
            }
            uint32_t bf[2][4];
            #pragma unroll
            for (int nj = 0; nj < 2; nj++) {
                const int n0 = wc * 32 + nj * 16;
                const uint32_t addr = bT + (uint32_t)(n0 + (lane & 15)) * SROW_B
                                      + kb + ((lane >> 4) << 4);
                LDMX4(bf[nj], addr);
            }
            #pragma unroll
            for (int mi = 0; mi < 4; mi++)
                #pragma unroll
                for (int ni = 0; ni < 4; ni++) {
                    const uint32_t b0v = bf[ni >> 1][ni & 1];
                    const uint32_t b1v = bf[ni >> 1][(ni & 1) + 2];
                    MMA_BF16(acc[mi][ni], af[mi], b0v, b1v);
                }
        }
        __syncthreads();
    }

    // epilogue
    #pragma unroll
    for (int mi = 0; mi < 4; mi++) {
        const int r0 = rowBase + wr * 64 + mi * 16 + (lane >> 2);
        #pragma unroll
        for (int ni = 0; ni < 4; ni++) {
            const int c = colBase + wc * 32 + ni * 8 + (lane & 3) * 2;
            const float b0c = bout[c], b1c = bout[c + 1];
            float2 v0 = make_float2(acc[mi][ni][0] + b0c, acc[mi][ni][1] + b1c);
            float2 v1 = make_float2(acc[mi][ni][2] + b0c, acc[mi][ni][3] + b1c);
            *(float2*)&out[(size_t)r0 * H_ + c]       = v0;
            *(float2*)&out[(size_t)(r0 + 8) * H_ + c] = v1;
        }
    }
}

// ============================================================
// launch
// ============================================================
extern "C" void kernel_launch(void* const* d_in, const int* in_sizes, int n_in,
                              void* d_out, int out_size) {
    const float* x     = (const float*)d_in[0];
    const float* A_log = (const float*)d_in[1];
    const float* WB    = (const float*)d_in[2];
    const float* WC    = (const float*)d_in[3];
    const float* Dv    = (const float*)d_in[4];
    const float* Wg    = (const float*)d_in[5];
    const float* bg    = (const float*)d_in[6];
    const float* Wout  = (const float*)d_in[7];
    const float* bout  = (const float*)d_in[8];
    const float* gamma = (const float*)d_in[9];
    const float* beta  = (const float*)d_in[10];

    float* out = (float*)d_out;
    float* finalState = (out_size >= M_ * H_ + B_ * S_) ? out + (size_t)M_ * H_ : nullptr;

    static int smemSet = 0;
    if (!smemSet) {
        cudaFuncSetAttribute(outGemmMMA, cudaFuncAttributeMaxDynamicSharedMemorySize, SMEM_D);
        smemSet = 1;
    }

    wSplit<<<H_*H_/1024, 256>>>(Wout);
    uGemm<<<M_/64, 256>>>(x, Wg, bg, WB);
    scanLocal<<<B_*NCH, S_>>>(A_log);
    scanCarry<<<1, B_*S_>>>(A_log, finalState);
    scanStates<<<B_*NCH, S_>>>(A_log);
    yLN<<<M_, 256>>>(x, WC, Dv, gamma, beta);
    dim3 gD(M_/128, H_/128);
    outGemmMMA<<<gD, 256, SMEM_D>>>(bout, out);
}

// round 6
// speedup vs baseline: 3.9357x; 2.9479x over previous
#include <cuda_runtime.h>
#include <cuda_bf16.h>
#include <cuda_fp16.h>
#include <math.h>
#include <stdint.h>

#define B_   4
#define T_   4096
#define H_   1024
#define S_   64
#define M_   (B_*T_)     // 16384 rows
#define NCH  64
#define TC   64
#define LN_EPSF 1e-5f

// ---- scratch ----
__device__ float g_u[M_*S_];
__device__ float g_L[B_*NCH*S_];
__device__ float g_E[B_*NCH*S_];
__device__ float g_states[M_*S_];
__device__ __half g_hn_hi[(size_t)M_*H_];          // 32 MB
__device__ __half g_hn_lo[(size_t)M_*H_];          // 32 MB
__device__ __half g_wo_hi[(size_t)H_*H_];          // 2 MB  (fp16, hi only: 2-seg)
__device__ __nv_bfloat16 g_x_hi[(size_t)M_*H_];    // 32 MB
__device__ __nv_bfloat16 g_x_lo[(size_t)M_*H_];    // 32 MB
__device__ __nv_bfloat16 g_wgb_hi[128*H_];         // interleaved [2s]=Wg[s], [2s+1]=WB[s]
__device__ __nv_bfloat16 g_wgb_lo[128*H_];

// ============================================================
// PTX helpers (sm_80+ portable)
// ============================================================
__device__ __forceinline__ uint32_t smem_u32(const void* p) {
    uint32_t a;
    asm("{ .reg .u64 t; cvta.to.shared.u64 t, %1; cvt.u32.u64 %0, t; }" : "=r"(a) : "l"(p));
    return a;
}
#define CP_ASYNC16(dst, src) \
    asm volatile("cp.async.cg.shared.global [%0], [%1], 16;" :: "r"(dst), "l"(src) : "memory")
#define CP_COMMIT() asm volatile("cp.async.commit_group;" ::: "memory")
#define CP_WAIT0()  asm volatile("cp.async.wait_group 0;" ::: "memory")

#define LDMX4(r, addr) \
    asm volatile("ldmatrix.sync.aligned.m8n8.x4.shared.b16 {%0,%1,%2,%3}, [%4];" \
        : "=r"((r)[0]), "=r"((r)[1]), "=r"((r)[2]), "=r"((r)[3]) : "r"(addr))

#define MMA_BF16(c, a, b0v, b1v) \
    asm volatile("mma.sync.aligned.m16n8k16.row.col.f32.bf16.bf16.f32 " \
        "{%0,%1,%2,%3},{%4,%5,%6,%7},{%8,%9},{%0,%1,%2,%3};" \
        : "+f"((c)[0]), "+f"((c)[1]), "+f"((c)[2]), "+f"((c)[3]) \
        : "r"((a)[0]), "r"((a)[1]), "r"((a)[2]), "r"((a)[3]), "r"(b0v), "r"(b1v))

#define MMA_F16(c, a, b0v, b1v) \
    asm volatile("mma.sync.aligned.m16n8k16.row.col.f32.f16.f16.f32 " \
        "{%0,%1,%2,%3},{%4,%5,%6,%7},{%8,%9},{%0,%1,%2,%3};" \
        : "+f"((c)[0]), "+f"((c)[1]), "+f"((c)[2]), "+f"((c)[3]) \
        : "r"((a)[0]), "r"((a)[1]), "r"((a)[2]), "r"((a)[3]), "r"(b0v), "r"(b1v))

// ============================================================
// split kernels
// ============================================================
__global__ void __launch_bounds__(256) xSplit(const float* __restrict__ x) {
    const size_t base = (size_t)blockIdx.x * 1024 + threadIdx.x * 4;
    float4 v = *(const float4*)&x[base];
    float vv[4] = {v.x, v.y, v.z, v.w};
    #pragma unroll
    for (int t = 0; t < 4; t++) {
        __nv_bfloat16 hi = __float2bfloat16(vv[t]);
        g_x_hi[base + t] = hi;
        g_x_lo[base + t] = __float2bfloat16(vv[t] - __bfloat162float(hi));
    }
}

__global__ void __launch_bounds__(256) wSplit(const float* __restrict__ Wout) {
    const int base = (blockIdx.x * 256 + threadIdx.x) * 4;
    #pragma unroll
    for (int t = 0; t < 4; t++)
        g_wo_hi[base + t] = __float2half_rn(Wout[base + t]);
}

__global__ void __launch_bounds__(256) wgbSplit(const float* __restrict__ Wg,
                                                const float* __restrict__ WB) {
    const int r = blockIdx.x;                     // packed row 0..127
    const int s = r >> 1;
    const float* src = (r & 1) ? &WB[(size_t)s * H_] : &Wg[(size_t)s * H_];
    for (int k = threadIdx.x * 4; k < H_; k += 1024) {
        #pragma unroll
        for (int t = 0; t < 4; t++) {
            float v = src[k + t];
            __nv_bfloat16 hi = __float2bfloat16(v);
            g_wgb_hi[(size_t)r * H_ + k + t] = hi;
            g_wgb_lo[(size_t)r * H_ + k + t] = __float2bfloat16(v - __bfloat162float(hi));
        }
    }
}

// ============================================================
// shared GEMM geometry
// ============================================================
#define KT     64
#define SROW_B 144           // bytes per smem row (72 x b16)
#define STILE  (128*SROW_B)  // 18432
#define SMEM_D (4*STILE)     // 73728

// ============================================================
// Kernel A: u via bf16 3-seg MMA: x @ [Wg;WB interleaved]^T, fused sigmoid*mul
// grid (M_/128, 1), K' = 3072
// ============================================================
__global__ void __launch_bounds__(256, 2) uGemmMMA(const float* __restrict__ bg) {
    extern __shared__ char sm[];
    const uint32_t smb = smem_u32(sm);
    const int tid = threadIdx.x;
    const int lane = tid & 31, w = tid >> 5;
    const int wr = w >> 2, wc = w & 3;
    const int rowBase = blockIdx.x * 128;

    auto loadStage = [&](int stage, int it) {
        const int seg = it >> 4;
        const int k0  = (it & 15) * KT;
        const __nv_bfloat16* Asrc = (seg == 1) ? g_x_lo : g_x_hi;
        const __nv_bfloat16* Bsrc = (seg == 2) ? g_wgb_lo : g_wgb_hi;
        const uint32_t aB = smb + stage * 2 * STILE;
        const uint32_t bB = aB + STILE;
        #pragma unroll
        for (int t = 0; t < 4; t++) {
            const int c = tid + t * 256;
            const int r = c >> 3, j = c & 7;
            CP_ASYNC16(aB + r * SROW_B + j * 16, &Asrc[(size_t)(rowBase + r) * H_ + k0 + j * 8]);
            CP_ASYNC16(bB + r * SROW_B + j * 16, &Bsrc[(size_t)r * H_ + k0 + j * 8]);
        }
        CP_COMMIT();
    };

    float acc[4][4][4];
    #pragma unroll
    for (int i = 0; i < 4; i++)
        #pragma unroll
        for (int j = 0; j < 4; j++)
            #pragma unroll
            for (int q = 0; q < 4; q++) acc[i][j][q] = 0.0f;

    loadStage(0, 0);
    const int NIT = 48;
    for (int it = 0; it < NIT; it++) {
        const int stage = it & 1;
        CP_WAIT0();
        __syncthreads();
        if (it + 1 < NIT) loadStage(stage ^ 1, it + 1);
        const uint32_t aT = smb + stage * 2 * STILE;
        const uint32_t bT = aT + STILE;
        #pragma unroll
        for (int ks = 0; ks < 4; ks++) {
            const int kb = ks * 32;
            uint32_t af[4][4];
            #pragma unroll
            for (int mi = 0; mi < 4; mi++) {
                const uint32_t addr = aT + (uint32_t)(wr * 64 + mi * 16 + (lane & 15)) * SROW_B
                                      + kb + ((lane >> 4) << 4);
                LDMX4(af[mi], addr);
            }
            uint32_t bf[2][4];
            #pragma unroll
            for (int nj = 0; nj < 2; nj++) {
                const uint32_t addr = bT + (uint32_t)(wc * 32 + nj * 16 + (lane & 15)) * SROW_B
                                      + kb + ((lane >> 4) << 4);
                LDMX4(bf[nj], addr);
            }
            #pragma unroll
            for (int mi = 0; mi < 4; mi++)
                #pragma unroll
                for (int ni = 0; ni < 4; ni++)
                    MMA_BF16(acc[mi][ni], af[mi], bf[ni >> 1][ni & 1], bf[ni >> 1][(ni & 1) + 2]);
        }
        __syncthreads();
    }

    // epilogue: cols (c, c+1) = (gate logit s, Bx s), s = c/2
    #pragma unroll
    for (int mi = 0; mi < 4; mi++) {
        const int r0 = rowBase + wr * 64 + mi * 16 + (lane >> 2);
        #pragma unroll
        for (int ni = 0; ni < 4; ni++) {
            const int c = wc * 32 + ni * 8 + (lane & 3) * 2;
            const int s = c >> 1;
            const float bgs = bg[s];
            float gate0 = 1.0f / (1.0f + expf(-(acc[mi][ni][0] + bgs)));
            float gate1 = 1.0f / (1.0f + expf(-(acc[mi][ni][2] + bgs)));
            g_u[(size_t)r0 * S_ + s]       = gate0 * acc[mi][ni][1];
            g_u[(size_t)(r0 + 8) * S_ + s] = gate1 * acc[mi][ni][3];
        }
    }
}

// ============================================================
// Scan kernels
// ============================================================
__global__ void scanLocal(const float* __restrict__ A_log) {
    const int b = blockIdx.x / NCH, c = blockIdx.x % NCH;
    const int s = threadIdx.x;
    const float a = expf(A_log[s]);
    const float* up = &g_u[((size_t)(b * T_) + c * TC) * S_ + s];
    float st = 0.0f;
    #pragma unroll 8
    for (int i = 0; i < TC; i++) st = fmaf(a, st, up[i * S_]);
    g_L[((size_t)b * NCH + c) * S_ + s] = st;
}

__global__ void scanCarry(const float* __restrict__ A_log, float* __restrict__ finalState) {
    const int tid = threadIdx.x;
    const int b = tid / S_, s = tid % S_;
    const float a = expf(A_log[s]);
    float aTC = 1.0f;
    #pragma unroll
    for (int i = 0; i < TC; i++) aTC *= a;
    float E = 0.0f;
    for (int c = 0; c < NCH; c++) {
        g_E[((size_t)b * NCH + c) * S_ + s] = E;
        E = fmaf(aTC, E, g_L[((size_t)b * NCH + c) * S_ + s]);
    }
    if (finalState) finalState[b * S_ + s] = E;
}

__global__ void scanStates(const float* __restrict__ A_log) {
    const int b = blockIdx.x / NCH, c = blockIdx.x % NCH;
    const int s = threadIdx.x;
    const float a = expf(A_log[s]);
    float st = g_E[((size_t)b * NCH + c) * S_ + s];
    const size_t base = ((size_t)(b * T_) + c * TC) * S_ + s;
    #pragma unroll 8
    for (int i = 0; i < TC; i++) {
        st = fmaf(a, st, g_u[base + (size_t)i * S_]);
        g_states[base + (size_t)i * S_] = st;
    }
}

// ============================================================
// Kernel C: tiled yLN. 16 rows/block, 512 threads, thread owns 2 cols x 16 rows.
// WC read once per block (256KB) -> L2 traffic 256MB total.
// ============================================================
__global__ void __launch_bounds__(512) yLNT(const float* __restrict__ x,
                                            const float* __restrict__ WC,
                                            const float* __restrict__ Dv,
                                            const float* __restrict__ gamma,
                                            const float* __restrict__ beta) {
    __shared__ float st[16][64];
    __shared__ float redS[16][16], redQ[16][16];
    __shared__ float muA[16], invA[16];
    const int tid = threadIdx.x;
    const int lane = tid & 31, w = tid >> 5;
    const int rowBase = blockIdx.x * 16;
    const int c0 = tid * 2;

    ((float2*)st)[tid] = ((const float2*)(g_states + (size_t)rowBase * S_))[tid];
    __syncthreads();

    float acc0[16], acc1[16];
    #pragma unroll
    for (int r = 0; r < 16; r++) { acc0[r] = 0.0f; acc1[r] = 0.0f; }

    const float4* wc0 = (const float4*)&WC[(size_t)c0 * S_];
    const float4* wc1 = (const float4*)&WC[(size_t)(c0 + 1) * S_];
    #pragma unroll 4
    for (int s4 = 0; s4 < 16; s4++) {
        float4 w0 = wc0[s4], w1 = wc1[s4];
        #pragma unroll
        for (int r = 0; r < 16; r++) {
            float4 sv = *(const float4*)&st[r][s4 * 4];
            acc0[r] = fmaf(w0.x, sv.x, fmaf(w0.y, sv.y, fmaf(w0.z, sv.z, fmaf(w0.w, sv.w, acc0[r]))));
            acc1[r] = fmaf(w1.x, sv.x, fmaf(w1.y, sv.y, fmaf(w1.z, sv.z, fmaf(w1.w, sv.w, acc1[r]))));
        }
    }

    const float d0 = Dv[c0] + 1.0f, d1 = Dv[c0 + 1] + 1.0f;
    #pragma unroll
    for (int r = 0; r < 16; r++) {
        float2 xv = *(const float2*)&x[(size_t)(rowBase + r) * H_ + c0];
        float h0 = fmaf(d0, xv.x, acc0[r]);
        float h1 = fmaf(d1, xv.y, acc1[r]);
        acc0[r] = h0; acc1[r] = h1;
        float sm = h0 + h1;
        float sq = fmaf(h0, h0, h1 * h1);
        #pragma unroll
        for (int o = 16; o > 0; o >>= 1) {
            sm += __shfl_down_sync(0xffffffffu, sm, o);
            sq += __shfl_down_sync(0xffffffffu, sq, o);
        }
        if (lane == 0) { redS[w][r] = sm; redQ[w][r] = sq; }
    }
    __syncthreads();
    if (tid < 16) {
        float s = 0.0f, q = 0.0f;
        #pragma unroll
        for (int i = 0; i < 16; i++) { s += redS[i][tid]; q += redQ[i][tid]; }
        float mu = s * (1.0f / H_);
        float var = q * (1.0f / H_) - mu * mu;
        muA[tid] = mu;
        invA[tid] = rsqrtf(var + LN_EPSF);
    }
    __syncthreads();

    const float g0 = gamma[c0], g1 = gamma[c0 + 1];
    const float b0 = beta[c0],  b1 = beta[c0 + 1];
    #pragma unroll
    for (int r = 0; r < 16; r++) {
        const float mu = muA[r], inv = invA[r];
        float v0 = fmaf((acc0[r] - mu) * inv, g0, b0);
        float v1 = fmaf((acc1[r] - mu) * inv, g1, b1);
        __half h0 = __float2half_rn(v0);
        __half h1 = __float2half_rn(v1);
        __half l0 = __float2half_rn(v0 - __half2float(h0));
        __half l1 = __float2half_rn(v1 - __half2float(h1));
        const size_t off = (size_t)(rowBase + r) * H_ + c0;
        *(__half2*)&g_hn_hi[off] = __halves2half2(h0, h1);
        *(__half2*)&g_hn_lo[off] = __halves2half2(l0, l1);
    }
}

// ============================================================
// Kernel D: out = hn @ Wout^T + bout, fp16 2-seg MMA (K' = 2048)
//   seg0: A=hn_hi B=wo_hi ; seg1: A=hn_lo B=wo_hi
// ============================================================
__global__ void __launch_bounds__(256, 2) outGemmMMA(const float* __restrict__ bout,
                                                     float* __restrict__ out) {
    extern __shared__ char sm[];
    const uint32_t smb = smem_u32(sm);
    const int tid = threadIdx.x;
    const int lane = tid & 31, w = tid >> 5;
    const int wr = w >> 2, wc = w & 3;
    const int rowBase = blockIdx.x * 128;
    const int colBase = blockIdx.y * 128;

    auto loadStage = [&](int stage, int it) {
        const int seg = it >> 4;
        const int k0  = (it & 15) * KT;
        const __half* Asrc = seg ? g_hn_lo : g_hn_hi;
        const uint32_t aB = smb + stage * 2 * STILE;
        const uint32_t bB = aB + STILE;
        #pragma unroll
        for (int t = 0; t < 4; t++) {
            const int c = tid + t * 256;
            const int r = c >> 3, j = c & 7;
            CP_ASYNC16(aB + r * SROW_B + j * 16, &Asrc[(size_t)(rowBase + r) * H_ + k0 + j * 8]);
            CP_ASYNC16(bB + r * SROW_B + j * 16, &g_wo_hi[(size_t)(colBase + r) * H_ + k0 + j * 8]);
        }
        CP_COMMIT();
    };

    float acc[4][4][4];
    #pragma unroll
    for (int i = 0; i < 4; i++)
        #pragma unroll
        for (int j = 0; j < 4; j++)
            #pragma unroll
            for (int q = 0; q < 4; q++) acc[i][j][q] = 0.0f;

    loadStage(0, 0);
    const int NIT = 32;
    for (int it = 0; it < NIT; it++) {
        const int stage = it & 1;
        CP_WAIT0();
        __syncthreads();
        if (it + 1 < NIT) loadStage(stage ^ 1, it + 1);
        const uint32_t aT = smb + stage * 2 * STILE;
        const uint32_t bT = aT + STILE;
        #pragma unroll
        for (int ks = 0; ks < 4; ks++) {
            const int kb = ks * 32;
            uint32_t af[4][4];
            #pragma unroll
            for (int mi = 0; mi < 4; mi++) {
                const uint32_t addr = aT + (uint32_t)(wr * 64 + mi * 16 + (lane & 15)) * SROW_B
                                      + kb + ((lane >> 4) << 4);
                LDMX4(af[mi], addr);
            }
            uint32_t bf[2][4];
            #pragma unroll
            for (int nj = 0; nj < 2; nj++) {
                const uint32_t addr = bT + (uint32_t)(wc * 32 + nj * 16 + (lane & 15)) * SROW_B
                                      + kb + ((lane >> 4) << 4);
                LDMX4(bf[nj], addr);
            }
            #pragma unroll
            for (int mi = 0; mi < 4; mi++)
                #pragma unroll
                for (int ni = 0; ni < 4; ni++)
                    MMA_F16(acc[mi][ni], af[mi], bf[ni >> 1][ni & 1], bf[ni >> 1][(ni & 1) + 2]);
        }
        __syncthreads();
    }

    #pragma unroll
    for (int mi = 0; mi < 4; mi++) {
        const int r0 = rowBase + wr * 64 + mi * 16 + (lane >> 2);
        #pragma unroll
        for (int ni = 0; ni < 4; ni++) {
            const int c = colBase + wc * 32 + ni * 8 + (lane & 3) * 2;
            const float b0c = bout[c], b1c = bout[c + 1];
            float2 v0 = make_float2(acc[mi][ni][0] + b0c, acc[mi][ni][1] + b1c);
            float2 v1 = make_float2(acc[mi][ni][2] + b0c, acc[mi][ni][3] + b1c);
            *(float2*)&out[(size_t)r0 * H_ + c]       = v0;
            *(float2*)&out[(size_t)(r0 + 8) * H_ + c] = v1;
        }
    }
}

// ============================================================
// launch
// ============================================================
extern "C" void kernel_launch(void* const* d_in, const int* in_sizes, int n_in,
                              void* d_out, int out_size) {
    const float* x     = (const float*)d_in[0];
    const float* A_log = (const float*)d_in[1];
    const float* WB    = (const float*)d_in[2];
    const float* WC    = (const float*)d_in[3];
    const float* Dv    = (const float*)d_in[4];
    const float* Wg    = (const float*)d_in[5];
    const float* bg    = (const float*)d_in[6];
    const float* Wout  = (const float*)d_in[7];
    const float* bout  = (const float*)d_in[8];
    const float* gamma = (const float*)d_in[9];
    const float* beta  = (const float*)d_in[10];

    float* out = (float*)d_out;
    float* finalState = (out_size >= M_ * H_ + B_ * S_) ? out + (size_t)M_ * H_ : nullptr;

    cudaFuncSetAttribute(outGemmMMA, cudaFuncAttributeMaxDynamicSharedMemorySize, SMEM_D);
    cudaFuncSetAttribute(uGemmMMA,   cudaFuncAttributeMaxDynamicSharedMemorySize, SMEM_D);

    wSplit<<<H_*H_/1024, 256>>>(Wout);
    wgbSplit<<<128, 256>>>(Wg, WB);
    xSplit<<<M_*H_/1024, 256>>>(x);
    uGemmMMA<<<M_/128, 256, SMEM_D>>>(bg);
    scanLocal<<<B_*NCH, S_>>>(A_log);
    scanCarry<<<1, B_*S_>>>(A_log, finalState);
    scanStates<<<B_*NCH, S_>>>(A_log);
    yLNT<<<M_/16, 512>>>(x, WC, Dv, gamma, beta);
    dim3 gD(M_/128, H_/128);
    outGemmMMA<<<gD, 256, SMEM_D>>>(bout, out);
}

// round 7
// speedup vs baseline: 5.2977x; 1.3461x over previous
#include <cuda_runtime.h>
#include <cuda_bf16.h>
#include <cuda_fp16.h>
#include <math.h>
#include <stdint.h>

#define B_   4
#define T_   4096
#define H_   1024
#define S_   64
#define M_   (B_*T_)     // 16384 rows
#define NCH  64
#define TC   64
#define LN_EPSF 1e-5f

// ---- scratch ----
__device__ float g_u[M_*S_];
__device__ float g_L[B_*NCH*S_];
__device__ float g_E[B_*NCH*S_];
__device__ float g_states[M_*S_];
__device__ __half g_hn_hi[(size_t)M_*H_];          // 32 MB
__device__ __half g_wo_hi[(size_t)H_*H_];          // 2 MB
__device__ __nv_bfloat16 g_x_hi[(size_t)M_*H_];    // 32 MB
__device__ __nv_bfloat16 g_x_lo[(size_t)M_*H_];    // 32 MB
__device__ __nv_bfloat16 g_wgb_hi[128*H_];         // interleaved [2s]=Wg[s], [2s+1]=WB[s]
__device__ __nv_bfloat16 g_wgb_lo[128*H_];

// ============================================================
// PTX helpers (sm_80+ portable)
// ============================================================
__device__ __forceinline__ uint32_t smem_u32(const void* p) {
    uint32_t a;
    asm("{ .reg .u64 t; cvta.to.shared.u64 t, %1; cvt.u32.u64 %0, t; }" : "=r"(a) : "l"(p));
    return a;
}
#define CP_ASYNC16(dst, src) \
    asm volatile("cp.async.cg.shared.global [%0], [%1], 16;" :: "r"(dst), "l"(src) : "memory")
#define CP_COMMIT() asm volatile("cp.async.commit_group;" ::: "memory")
#define CP_WAIT0()  asm volatile("cp.async.wait_group 0;" ::: "memory")

#define LDMX4(r, addr) \
    asm volatile("ldmatrix.sync.aligned.m8n8.x4.shared.b16 {%0,%1,%2,%3}, [%4];" \
        : "=r"((r)[0]), "=r"((r)[1]), "=r"((r)[2]), "=r"((r)[3]) : "r"(addr))

#define MMA_BF16(c, a, b0v, b1v) \
    asm volatile("mma.sync.aligned.m16n8k16.row.col.f32.bf16.bf16.f32 " \
        "{%0,%1,%2,%3},{%4,%5,%6,%7},{%8,%9},{%0,%1,%2,%3};" \
        : "+f"((c)[0]), "+f"((c)[1]), "+f"((c)[2]), "+f"((c)[3]) \
        : "r"((a)[0]), "r"((a)[1]), "r"((a)[2]), "r"((a)[3]), "r"(b0v), "r"(b1v))

#define MMA_F16(c, a, b0v, b1v) \
    asm volatile("mma.sync.aligned.m16n8k16.row.col.f32.f16.f16.f32 " \
        "{%0,%1,%2,%3},{%4,%5,%6,%7},{%8,%9},{%0,%1,%2,%3};" \
        : "+f"((c)[0]), "+f"((c)[1]), "+f"((c)[2]), "+f"((c)[3]) \
        : "r"((a)[0]), "r"((a)[1]), "r"((a)[2]), "r"((a)[3]), "r"(b0v), "r"(b1v))

// ============================================================
// split kernels
// ============================================================
__global__ void __launch_bounds__(256) xSplit(const float* __restrict__ x) {
    const size_t base = (size_t)blockIdx.x * 1024 + threadIdx.x * 4;
    float4 v = *(const float4*)&x[base];
    float vv[4] = {v.x, v.y, v.z, v.w};
    #pragma unroll
    for (int t = 0; t < 4; t++) {
        __nv_bfloat16 hi = __float2bfloat16(vv[t]);
        g_x_hi[base + t] = hi;
        g_x_lo[base + t] = __float2bfloat16(vv[t] - __bfloat162float(hi));
    }
}

__global__ void __launch_bounds__(256) wSplit(const float* __restrict__ Wout) {
    const int base = (blockIdx.x * 256 + threadIdx.x) * 4;
    #pragma unroll
    for (int t = 0; t < 4; t++)
        g_wo_hi[base + t] = __float2half_rn(Wout[base + t]);
}

__global__ void __launch_bounds__(256) wgbSplit(const float* __restrict__ Wg,
                                                const float* __restrict__ WB) {
    const int r = blockIdx.x;
    const int s = r >> 1;
    const float* src = (r & 1) ? &WB[(size_t)s * H_] : &Wg[(size_t)s * H_];
    for (int k = threadIdx.x * 4; k < H_; k += 1024) {
        #pragma unroll
        for (int t = 0; t < 4; t++) {
            float v = src[k + t];
            __nv_bfloat16 hi = __float2bfloat16(v);
            g_wgb_hi[(size_t)r * H_ + k + t] = hi;
            g_wgb_lo[(size_t)r * H_ + k + t] = __float2bfloat16(v - __bfloat162float(hi));
        }
    }
}

// ============================================================
// shared GEMM geometry
// ============================================================
#define KT     64
#define SROW_B 144           // bytes per smem row (72 x b16)
#define STILE  (128*SROW_B)  // 18432 (128-row tile)
#define SMEM_D (4*STILE)     // 73728

// ============================================================
// Kernel A: u via bf16 3-seg MMA, MT=64 tile -> grid 256 CTAs.
// x @ [Wg;WB interleaved]^T, fused sigmoid*mul. K' = 3072.
// ============================================================
#define UA_TILE (64*SROW_B)              // 9216
#define UB_TILE (128*SROW_B)             // 18432
#define U_STAGE (UA_TILE + UB_TILE)      // 27648
#define SMEM_U  (2*U_STAGE)              // 55296

__global__ void __launch_bounds__(256, 2) uGemmMMA(const float* __restrict__ bg) {
    extern __shared__ char sm[];
    const uint32_t smb = smem_u32(sm);
    const int tid = threadIdx.x;
    const int lane = tid & 31, w = tid >> 5;
    const int wr = w >> 2, wc = w & 3;            // 2 x 4 warps; warp tile 32x32
    const int rowBase = blockIdx.x * 64;

    auto loadStage = [&](int stage, int it) {
        const int seg = it >> 4;
        const int k0  = (it & 15) * KT;
        const __nv_bfloat16* Asrc = (seg == 1) ? g_x_lo : g_x_hi;
        const __nv_bfloat16* Bsrc = (seg == 2) ? g_wgb_lo : g_wgb_hi;
        const uint32_t aB = smb + stage * U_STAGE;
        const uint32_t bB = aB + UA_TILE;
        #pragma unroll
        for (int t = 0; t < 2; t++) {             // A: 64 rows x 8 chunks = 512
            const int c = tid + t * 256;
            const int r = c >> 3, j = c & 7;
            CP_ASYNC16(aB + r * SROW_B + j * 16, &Asrc[(size_t)(rowBase + r) * H_ + k0 + j * 8]);
        }
        #pragma unroll
        for (int t = 0; t < 4; t++) {             // B: 128 rows x 8 chunks = 1024
            const int c = tid + t * 256;
            const int r = c >> 3, j = c & 7;
            CP_ASYNC16(bB + r * SROW_B + j * 16, &Bsrc[(size_t)r * H_ + k0 + j * 8]);
        }
        CP_COMMIT();
    };

    float acc[2][4][4];
    #pragma unroll
    for (int i = 0; i < 2; i++)
        #pragma unroll
        for (int j = 0; j < 4; j++)
            #pragma unroll
            for (int q = 0; q < 4; q++) acc[i][j][q] = 0.0f;

    loadStage(0, 0);
    const int NIT = 48;
    for (int it = 0; it < NIT; it++) {
        const int stage = it & 1;
        CP_WAIT0();
        __syncthreads();
        if (it + 1 < NIT) loadStage(stage ^ 1, it + 1);
        const uint32_t aT = smb + stage * U_STAGE;
        const uint32_t bT = aT + UA_TILE;
        #pragma unroll
        for (int ks = 0; ks < 4; ks++) {
            const int kb = ks * 32;
            uint32_t af[2][4];
            #pragma unroll
            for (int mi = 0; mi < 2; mi++) {
                const uint32_t addr = aT + (uint32_t)(wr * 32 + mi * 16 + (lane & 15)) * SROW_B
                                      + kb + ((lane >> 4) << 4);
                LDMX4(af[mi], addr);
            }
            uint32_t bf[2][4];
            #pragma unroll
            for (int nj = 0; nj < 2; nj++) {
                const uint32_t addr = bT + (uint32_t)(wc * 32 + nj * 16 + (lane & 15)) * SROW_B
                                      + kb + ((lane >> 4) << 4);
                LDMX4(bf[nj], addr);
            }
            #pragma unroll
            for (int mi = 0; mi < 2; mi++)
                #pragma unroll
                for (int ni = 0; ni < 4; ni++)
                    MMA_BF16(acc[mi][ni], af[mi], bf[ni >> 1][ni & 1], bf[ni >> 1][(ni & 1) + 2]);
        }
        __syncthreads();
    }

    // epilogue: cols (c, c+1) = (gate logit s, Bx s), s = c/2
    #pragma unroll
    for (int mi = 0; mi < 2; mi++) {
        const int r0 = rowBase + wr * 32 + mi * 16 + (lane >> 2);
        #pragma unroll
        for (int ni = 0; ni < 4; ni++) {
            const int c = wc * 32 + ni * 8 + (lane & 3) * 2;
            const int s = c >> 1;
            const float bgs = bg[s];
            float gate0 = 1.0f / (1.0f + expf(-(acc[mi][ni][0] + bgs)));
            float gate1 = 1.0f / (1.0f + expf(-(acc[mi][ni][2] + bgs)));
            g_u[(size_t)r0 * S_ + s]       = gate0 * acc[mi][ni][1];
            g_u[(size_t)(r0 + 8) * S_ + s] = gate1 * acc[mi][ni][3];
        }
    }
}

// ============================================================
// Scan kernels
// ============================================================
__global__ void scanLocal(const float* __restrict__ A_log) {
    const int b = blockIdx.x / NCH, c = blockIdx.x % NCH;
    const int s = threadIdx.x;
    const float a = expf(A_log[s]);
    const float* up = &g_u[((size_t)(b * T_) + c * TC) * S_ + s];
    float st = 0.0f;
    #pragma unroll 8
    for (int i = 0; i < TC; i++) st = fmaf(a, st, up[i * S_]);
    g_L[((size_t)b * NCH + c) * S_ + s] = st;
}

// batch-load g_L into registers first (MLP~64), then the serial chain is reg-only
__global__ void scanCarry(const float* __restrict__ A_log, float* __restrict__ finalState) {
    const int tid = threadIdx.x;
    const int b = tid / S_, s = tid % S_;
    const float a = expf(A_log[s]);
    float aTC = 1.0f;
    #pragma unroll
    for (int i = 0; i < TC; i++) aTC *= a;
    float L[NCH];
    #pragma unroll
    for (int c = 0; c < NCH; c++)
        L[c] = g_L[((size_t)b * NCH + c) * S_ + s];
    float E = 0.0f;
    #pragma unroll
    for (int c = 0; c < NCH; c++) {
        g_E[((size_t)b * NCH + c) * S_ + s] = E;
        E = fmaf(aTC, E, L[c]);
    }
    if (finalState) finalState[b * S_ + s] = E;
}

__global__ void scanStates(const float* __restrict__ A_log) {
    const int b = blockIdx.x / NCH, c = blockIdx.x % NCH;
    const int s = threadIdx.x;
    const float a = expf(A_log[s]);
    float st = g_E[((size_t)b * NCH + c) * S_ + s];
    const size_t base = ((size_t)(b * T_) + c * TC) * S_ + s;
    #pragma unroll 8
    for (int i = 0; i < TC; i++) {
        st = fmaf(a, st, g_u[base + (size_t)i * S_]);
        g_states[base + (size_t)i * S_] = st;
    }
}

// ============================================================
// Kernel C: tiled yLN -> fp16 hi only
// ============================================================
__global__ void __launch_bounds__(512) yLNT(const float* __restrict__ x,
                                            const float* __restrict__ WC,
                                            const float* __restrict__ Dv,
                                            const float* __restrict__ gamma,
                                            const float* __restrict__ beta) {
    __shared__ float st[16][64];
    __shared__ float redS[16][16], redQ[16][16];
    __shared__ float muA[16], invA[16];
    const int tid = threadIdx.x;
    const int lane = tid & 31, w = tid >> 5;
    const int rowBase = blockIdx.x * 16;
    const int c0 = tid * 2;

    ((float2*)st)[tid] = ((const float2*)(g_states + (size_t)rowBase * S_))[tid];
    __syncthreads();

    float acc0[16], acc1[16];
    #pragma unroll
    for (int r = 0; r < 16; r++) { acc0[r] = 0.0f; acc1[r] = 0.0f; }

    const float4* wc0 = (const float4*)&WC[(size_t)c0 * S_];
    const float4* wc1 = (const float4*)&WC[(size_t)(c0 + 1) * S_];
    #pragma unroll 4
    for (int s4 = 0; s4 < 16; s4++) {
        float4 w0 = wc0[s4], w1 = wc1[s4];
        #pragma unroll
        for (int r = 0; r < 16; r++) {
            float4 sv = *(const float4*)&st[r][s4 * 4];
            acc0[r] = fmaf(w0.x, sv.x, fmaf(w0.y, sv.y, fmaf(w0.z, sv.z, fmaf(w0.w, sv.w, acc0[r]))));
            acc1[r] = fmaf(w1.x, sv.x, fmaf(w1.y, sv.y, fmaf(w1.z, sv.z, fmaf(w1.w, sv.w, acc1[r]))));
        }
    }

    const float d0 = Dv[c0] + 1.0f, d1 = Dv[c0 + 1] + 1.0f;
    #pragma unroll
    for (int r = 0; r < 16; r++) {
        float2 xv = *(const float2*)&x[(size_t)(rowBase + r) * H_ + c0];
        float h0 = fmaf(d0, xv.x, acc0[r]);
        float h1 = fmaf(d1, xv.y, acc1[r]);
        acc0[r] = h0; acc1[r] = h1;
        float sm = h0 + h1;
        float sq = fmaf(h0, h0, h1 * h1);
        #pragma unroll
        for (int o = 16; o > 0; o >>= 1) {
            sm += __shfl_down_sync(0xffffffffu, sm, o);
            sq += __shfl_down_sync(0xffffffffu, sq, o);
        }
        if (lane == 0) { redS[w][r] = sm; redQ[w][r] = sq; }
    }
    __syncthreads();
    if (tid < 16) {
        float s = 0.0f, q = 0.0f;
        #pragma unroll
        for (int i = 0; i < 16; i++) { s += redS[i][tid]; q += redQ[i][tid]; }
        float mu = s * (1.0f / H_);
        float var = q * (1.0f / H_) - mu * mu;
        muA[tid] = mu;
        invA[tid] = rsqrtf(var + LN_EPSF);
    }
    __syncthreads();

    const float g0 = gamma[c0], g1 = gamma[c0 + 1];
    const float b0 = beta[c0],  b1 = beta[c0 + 1];
    #pragma unroll
    for (int r = 0; r < 16; r++) {
        const float mu = muA[r], inv = invA[r];
        float v0 = fmaf((acc0[r] - mu) * inv, g0, b0);
        float v1 = fmaf((acc1[r] - mu) * inv, g1, b1);
        const size_t off = (size_t)(rowBase + r) * H_ + c0;
        *(__half2*)&g_hn_hi[off] = __halves2half2(__float2half_rn(v0), __float2half_rn(v1));
    }
}

// ============================================================
// Kernel D: out = hn_hi @ wo_hi^T + bout, 1-seg fp16 MMA (K = 1024)
// ============================================================
__global__ void __launch_bounds__(256, 2) outGemmMMA(const float* __restrict__ bout,
                                                     float* __restrict__ out) {
    extern __shared__ char sm[];
    const uint32_t smb = smem_u32(sm);
    const int tid = threadIdx.x;
    const int lane = tid & 31, w = tid >> 5;
    const int wr = w >> 2, wc = w & 3;
    const int rowBase = blockIdx.x * 128;
    const int colBase = blockIdx.y * 128;

    auto loadStage = [&](int stage, int it) {
        const int k0  = it * KT;
        const uint32_t aB = smb + stage * 2 * STILE;
        const uint32_t bB = aB + STILE;
        #pragma unroll
        for (int t = 0; t < 4; t++) {
            const int c = tid + t * 256;
            const int r = c >> 3, j = c & 7;
            CP_ASYNC16(aB + r * SROW_B + j * 16, &g_hn_hi[(size_t)(rowBase + r) * H_ + k0 + j * 8]);
            CP_ASYNC16(bB + r * SROW_B + j * 16, &g_wo_hi[(size_t)(colBase + r) * H_ + k0 + j * 8]);
        }
        CP_COMMIT();
    };

    float acc[4][4][4];
    #pragma unroll
    for (int i = 0; i < 4; i++)
        #pragma unroll
        for (int j = 0; j < 4; j++)
            #pragma unroll
            for (int q = 0; q < 4; q++) acc[i][j][q] = 0.0f;

    loadStage(0, 0);
    const int NIT = 16;
    for (int it = 0; it < NIT; it++) {
        const int stage = it & 1;
        CP_WAIT0();
        __syncthreads();
        if (it + 1 < NIT) loadStage(stage ^ 1, it + 1);
        const uint32_t aT = smb + stage * 2 * STILE;
        const uint32_t bT = aT + STILE;
        #pragma unroll
        for (int ks = 0; ks < 4; ks++) {
            const int kb = ks * 32;
            uint32_t af[4][4];
            #pragma unroll
            for (int mi = 0; mi < 4; mi++) {
                const uint32_t addr = aT + (uint32_t)(wr * 64 + mi * 16 + (lane & 15)) * SROW_B
                                      + kb + ((lane >> 4) << 4);
                LDMX4(af[mi], addr);
            }
            uint32_t bf[2][4];
            #pragma unroll
            for (int nj = 0; nj < 2; nj++) {
                const uint32_t addr = bT + (uint32_t)(wc * 32 + nj * 16 + (lane & 15)) * SROW_B
                                      + kb + ((lane >> 4) << 4);
                LDMX4(bf[nj], addr);
            }
            #pragma unroll
            for (int mi = 0; mi < 4; mi++)
                #pragma unroll
                for (int ni = 0; ni < 4; ni++)
                    MMA_F16(acc[mi][ni], af[mi], bf[ni >> 1][ni & 1], bf[ni >> 1][(ni & 1) + 2]);
        }
        __syncthreads();
    }

    #pragma unroll
    for (int mi = 0; mi < 4; mi++) {
        const int r0 = rowBase + wr * 64 + mi * 16 + (lane >> 2);
        #pragma unroll
        for (int ni = 0; ni < 4; ni++) {
            const int c = colBase + wc * 32 + ni * 8 + (lane & 3) * 2;
            const float b0c = bout[c], b1c = bout[c + 1];
            float2 v0 = make_float2(acc[mi][ni][0] + b0c, acc[mi][ni][1] + b1c);
            float2 v1 = make_float2(acc[mi][ni][2] + b0c, acc[mi][ni][3] + b1c);
            *(float2*)&out[(size_t)r0 * H_ + c]       = v0;
            *(float2*)&out[(size_t)(r0 + 8) * H_ + c] = v1;
        }
    }
}

// ============================================================
// launch
// ============================================================
extern "C" void kernel_launch(void* const* d_in, const int* in_sizes, int n_in,
                              void* d_out, int out_size) {
    const float* x     = (const float*)d_in[0];
    const float* A_log = (const float*)d_in[1];
    const float* WB    = (const float*)d_in[2];
    const float* WC    = (const float*)d_in[3];
    const float* Dv    = (const float*)d_in[4];
    const float* Wg    = (const float*)d_in[5];
    const float* bg    = (const float*)d_in[6];
    const float* Wout  = (const float*)d_in[7];
    const float* bout  = (const float*)d_in[8];
    const float* gamma = (const float*)d_in[9];
    const float* beta  = (const float*)d_in[10];

    float* out = (float*)d_out;
    float* finalState = (out_size >= M_ * H_ + B_ * S_) ? out + (size_t)M_ * H_ : nullptr;

    cudaFuncSetAttribute(outGemmMMA, cudaFuncAttributeMaxDynamicSharedMemorySize, SMEM_D);
    cudaFuncSetAttribute(uGemmMMA,   cudaFuncAttributeMaxDynamicSharedMemorySize, SMEM_U);

    wSplit<<<H_*H_/1024, 256>>>(Wout);
    wgbSplit<<<128, 256>>>(Wg, WB);
    xSplit<<<M_*H_/1024, 256>>>(x);
    uGemmMMA<<<M_/64, 256, SMEM_U>>>(bg);
    scanLocal<<<B_*NCH, S_>>>(A_log);
    scanCarry<<<1, B_*S_>>>(A_log, finalState);
    scanStates<<<B_*NCH, S_>>>(A_log);
    yLNT<<<M_/16, 512>>>(x, WC, Dv, gamma, beta);
    dim3 gD(M_/128, H_/128);
    outGemmMMA<<<gD, 256, SMEM_D>>>(bout, out);
}